// round 10
// baseline (speedup 1.0000x reference)
#include <cuda_runtime.h>
#include <cstdint>

// VectorQuantizer N=65536, K=8192, D=256.
// R9: int8 dp4a filter + exact fp32 rescore (R2-bit-exact). vs R8: all per-tile
// smem atomics replaced by shfl-reduced register row-min (rows are warp-owned);
// single merged prep kernel (also aligns ncu -s 5 onto vq_main).

typedef unsigned long long u64;
typedef uint32_t u32;

#define NN     65536
#define KC     8192
#define DD     256
#define BM     128
#define BN     64
#define NTILES (KC / BN)     // 128
#define NTHR   256
#define CAP    32
#define WIN    6e-4f
#define RSTRD  264           // bytes per smem row (33 x 8B: conflict-free LDS.64)

// e ~ U(-1/8192, 1/8192) => |e|*SE < 127 exactly
#define SEF    1040384.0f    // 127 * 8192

__device__ u32   g_zq[(size_t)NN * (DD / 4)];   // packed int8, 4 dims per word
__device__ u32   g_eq[(size_t)KC * (DD / 4)];
__device__ float g_z2[NN];
__device__ float g_e2[KC];
__device__ float g_invS[NN];                    // 2 / (SZ_r * SE)

// smem byte offsets
#define SA    0                        // 128*264 = 33792
#define SB0   33792                    // 64*264 = 16896
#define SB1   50688
#define SZ2   67584                    // 128*4
#define SINV  68096
#define SMIN  68608                    // final per-row min (float)
#define SCNT  69120
#define SCD   69632                    // 128*CAP*4 = 16384
#define SCK   86016
#define SFI   102400
#define STOT  102912

__device__ __forceinline__ u32 s2u(const void* p) {
    u32 a;
    asm("{ .reg .u64 t; cvta.to.shared.u64 t, %1; cvt.u32.u64 %0, t; }"
        : "=r"(a) : "l"(p));
    return a;
}
__device__ __forceinline__ void cpa8(u32 dst, const void* src) {
    asm volatile("cp.async.ca.shared.global [%0], [%1], 8;\n" :: "r"(dst), "l"(src));
}

// ---------------- merged prep kernel (z2/e2 accumulation order preserved!) ----------------
__global__ void prep_all(const float* __restrict__ z, const float* __restrict__ emb) {
    int b = blockIdx.x, lane = threadIdx.x;
    if (b < KC) {
        const float* r = emb + (size_t)b * DD;
        #pragma unroll
        for (int h = 0; h < 2; ++h) {
            int w = lane + h * 32;
            int q0 = __float2int_rn(r[w * 4 + 0] * SEF);
            int q1 = __float2int_rn(r[w * 4 + 1] * SEF);
            int q2 = __float2int_rn(r[w * 4 + 2] * SEF);
            int q3 = __float2int_rn(r[w * 4 + 3] * SEF);
            q0 = max(-127, min(127, q0)); q1 = max(-127, min(127, q1));
            q2 = max(-127, min(127, q2)); q3 = max(-127, min(127, q3));
            g_eq[(size_t)b * 64 + w] = (u32)(q0 & 255) | ((u32)(q1 & 255) << 8)
                                     | ((u32)(q2 & 255) << 16) | ((u32)(q3 & 255) << 24);
        }
        if (lane == 0) {
            float s = 0.f;
            #pragma unroll 8
            for (int d = 0; d < DD; ++d) s = __fadd_rn(s, __fmul_rn(r[d], r[d]));
            g_e2[b] = s;
        }
    } else {
        int n = b - KC;
        const float* r = z + (size_t)n * DD;
        float m = 0.f;
        #pragma unroll
        for (int i = 0; i < DD / 32; ++i) m = fmaxf(m, fabsf(r[lane + i * 32]));
        #pragma unroll
        for (int s = 16; s > 0; s >>= 1) m = fmaxf(m, __shfl_xor_sync(0xffffffffu, m, s));
        float SZ = 127.0f / m;
        #pragma unroll
        for (int h = 0; h < 2; ++h) {
            int w = lane + h * 32;
            int q0 = __float2int_rn(r[w * 4 + 0] * SZ);
            int q1 = __float2int_rn(r[w * 4 + 1] * SZ);
            int q2 = __float2int_rn(r[w * 4 + 2] * SZ);
            int q3 = __float2int_rn(r[w * 4 + 3] * SZ);
            q0 = max(-127, min(127, q0)); q1 = max(-127, min(127, q1));
            q2 = max(-127, min(127, q2)); q3 = max(-127, min(127, q3));
            g_zq[(size_t)n * 64 + w] = (u32)(q0 & 255) | ((u32)(q1 & 255) << 8)
                                     | ((u32)(q2 & 255) << 16) | ((u32)(q3 & 255) << 24);
        }
        if (lane == 0) {
            g_invS[n] = 2.0f / (SZ * SEF);
            float s = 0.f;
            #pragma unroll 8
            for (int d = 0; d < DD; ++d) s = __fadd_rn(s, __fmul_rn(r[d], r[d]));
            g_z2[n] = s;
        }
    }
}

// ---------------- main kernel ----------------
__global__ __launch_bounds__(NTHR, 2)
void vq_main(const float* __restrict__ z, const float* __restrict__ emb,
             float* __restrict__ oq, float* __restrict__ ost,
             float* __restrict__ oidx)
{
    extern __shared__ char sm[];
    const u32 smb = s2u(sm);
    float* z2s    = (float*)(sm + SZ2);
    float* invSs  = (float*)(sm + SINV);
    float* rowMinF= (float*)(sm + SMIN);
    int*   cnt    = (int*)(sm + SCNT);
    float* candD  = (float*)(sm + SCD);
    int*   candK  = (int*)(sm + SCK);
    int*   fidx   = (int*)(sm + SFI);

    const int tid = threadIdx.x;
    const int tx  = tid & 15;           // code lane 0..15 (codes tx + 16j)
    const int ty  = tid >> 4;           // row lane 0..15 (rows ty + 16i)
    const int rowbase = blockIdx.x * BM;

    if (tid < BM) {
        cnt[tid]    = 0;
        z2s[tid]    = g_z2[rowbase + tid];
        invSs[tid]  = g_invS[rowbase + tid];
    }

    // group 0: A tile (int8, 128x256B) + B tile 0
    {
        const char* zq = (const char*)g_zq + (size_t)rowbase * DD;
        #pragma unroll 8
        for (int q = tid; q < BM * 32; q += NTHR) {        // 8B chunks
            int r = q >> 5, c = (q & 31) * 8;
            cpa8(smb + SA + (u32)(r * RSTRD + c), zq + (size_t)r * DD + c);
        }
        const char* eq = (const char*)g_eq;
        #pragma unroll 4
        for (int q = tid; q < BN * 32; q += NTHR) {
            int r = q >> 5, c = (q & 31) * 8;
            cpa8(smb + SB0 + (u32)(r * RSTRD + c), eq + (size_t)r * DD + c);
        }
        asm volatile("cp.async.commit_group;\n" ::);
    }
    __syncthreads();

    const uint2* Au = (const uint2*)(sm + SA);

    float runMin[8];
    #pragma unroll
    for (int i = 0; i < 8; ++i) runMin[i] = 3.4e38f;

    for (int t = 0; t < NTILES; ++t) {
        if (t + 1 < NTILES) {
            const char* eq = (const char*)g_eq + (size_t)(t + 1) * BN * DD;
            u32 bb = smb + (((t + 1) & 1) ? SB1 : SB0);
            #pragma unroll 4
            for (int q = tid; q < BN * 32; q += NTHR) {
                int r = q >> 5, c = (q & 31) * 8;
                cpa8(bb + (u32)(r * RSTRD + c), eq + (size_t)r * DD + c);
            }
            asm volatile("cp.async.commit_group;\n" ::);
            asm volatile("cp.async.wait_group 1;\n" ::);
        } else {
            asm volatile("cp.async.wait_group 0;\n" ::);
        }
        __syncthreads();

        const uint2* Bu = (const uint2*)(sm + ((t & 1) ? SB1 : SB0));

        int acc[8][4];
        #pragma unroll
        for (int i = 0; i < 8; ++i)
            #pragma unroll
            for (int j = 0; j < 4; ++j) acc[i][j] = 0;

        #pragma unroll 2
        for (int d8 = 0; d8 < 32; ++d8) {            // 8 dims per step
            uint2 za[8], eb[4];
            #pragma unroll
            for (int j = 0; j < 4; ++j) eb[j] = Bu[(tx + 16 * j) * 33 + d8];
            #pragma unroll
            for (int i = 0; i < 8; ++i) za[i] = Au[(ty + 16 * i) * 33 + d8];
            #pragma unroll
            for (int i = 0; i < 8; ++i)
                #pragma unroll
                for (int j = 0; j < 4; ++j) {
                    acc[i][j] = __dp4a((int)za[i].x, (int)eb[j].x, acc[i][j]);
                    acc[i][j] = __dp4a((int)za[i].y, (int)eb[j].y, acc[i][j]);
                }
        }

        // ---- epilogue: tile row-min via shfl (no atomics), then inserts ----
        int cb = t * BN;
        float e2v[4];
        #pragma unroll
        for (int j = 0; j < 4; ++j) e2v[j] = __ldg(g_e2 + cb + tx + 16 * j);

        float tmin[8];
        #pragma unroll
        for (int i = 0; i < 8; ++i) {
            int r = ty + 16 * i;
            float z2v = z2s[r], is = invSs[r];
            float mn = 3.4e38f;
            #pragma unroll
            for (int j = 0; j < 4; ++j)
                mn = fminf(mn, fmaf(-(float)acc[i][j], is, z2v + e2v[j]));
            tmin[i] = mn;
        }
        // reduce min over the 16 tx lanes (stays within half-warp)
        #pragma unroll
        for (int s = 1; s < 16; s <<= 1)
            #pragma unroll
            for (int i = 0; i < 8; ++i)
                tmin[i] = fminf(tmin[i], __shfl_xor_sync(0xffffffffu, tmin[i], s));
        #pragma unroll
        for (int i = 0; i < 8; ++i) runMin[i] = fminf(runMin[i], tmin[i]);

        // insert pass: recompute dv from live acc, threshold from register
        #pragma unroll
        for (int i = 0; i < 8; ++i) {
            int r = ty + 16 * i;
            float z2v = z2s[r], is = invSs[r];
            float thr = runMin[i] + WIN;
            #pragma unroll
            for (int j = 0; j < 4; ++j) {
                float dv = fmaf(-(float)acc[i][j], is, z2v + e2v[j]);
                if (dv <= thr) {
                    int pos = atomicAdd(&cnt[r], 1);
                    if (pos < CAP) {
                        candD[r * CAP + pos] = dv;
                        candK[r * CAP + pos] = cb + tx + 16 * j;
                    }
                }
            }
        }
        __syncthreads();
    }

    // publish final row mins (row owned by one warp; lane tx==0 writes)
    if (tx == 0) {
        #pragma unroll
        for (int i = 0; i < 8; ++i) rowMinF[ty + 16 * i] = runMin[i];
    }
    __syncthreads();

    // ---- exact rescore (replicates R2 arithmetic exactly) ----
    if (tid < BM) {
        int r = tid;
        size_t n = (size_t)rowbase + r;
        int c = cnt[r];
        if (c > CAP) {
            fidx[r] = -1;
        } else {
            float thrF = rowMinF[r] + WIN;
            float z2e = g_z2[n];
            const float* zr = z + n * DD;
            float bd = 0.f; int bk = -1;
            for (int i = 0; i < c; ++i) {
                if (candD[r * CAP + i] > thrF) continue;
                int k = candK[r * CAP + i];
                const float* er = emb + (size_t)k * DD;
                float lo = 0.f, hi = 0.f;
                #pragma unroll 4
                for (int d2 = 0; d2 < DD / 2; ++d2) {
                    lo = __fmaf_rn(__ldg(zr + 2 * d2),     __ldg(er + 2 * d2),     lo);
                    hi = __fmaf_rn(__ldg(zr + 2 * d2 + 1), __ldg(er + 2 * d2 + 1), hi);
                }
                float dot = __fadd_rn(lo, hi);
                float tt  = __fadd_rn(z2e, g_e2[k]);
                float dd  = __fadd_rn(tt, -2.0f * dot);
                if (bk < 0 || dd < bd || (dd == bd && k < bk)) { bd = dd; bk = k; }
            }
            fidx[r] = bk;
        }
    }
    __syncthreads();

    // ---- overflow fallback: full exact scan (cold) ----
    {
        float* redD = (float*)(sm + SB0);
        int*   redI = (int*)(sm + SB0 + NTHR * 4);
        for (int r = 0; r < BM; ++r) {
            if (fidx[r] != -1) continue;
            size_t n = (size_t)rowbase + r;
            const float* zr = z + n * DD;
            float z2e = g_z2[n];
            float bd = 0.f; int bk = -1;
            for (int k = tid; k < KC; k += NTHR) {
                const float* er = emb + (size_t)k * DD;
                float lo = 0.f, hi = 0.f;
                #pragma unroll 4
                for (int d2 = 0; d2 < DD / 2; ++d2) {
                    lo = __fmaf_rn(zr[2 * d2],     er[2 * d2],     lo);
                    hi = __fmaf_rn(zr[2 * d2 + 1], er[2 * d2 + 1], hi);
                }
                float dot = __fadd_rn(lo, hi);
                float dd  = __fadd_rn(__fadd_rn(z2e, g_e2[k]), -2.0f * dot);
                if (bk < 0 || dd < bd || (dd == bd && k < bk)) { bd = dd; bk = k; }
            }
            redD[tid] = bd; redI[tid] = bk;
            __syncthreads();
            if (tid == 0) {
                float B = redD[0]; int K2 = redI[0];
                for (int s2 = 1; s2 < NTHR; ++s2) {
                    float d = redD[s2]; int k2 = redI[s2];
                    if (k2 >= 0 && (K2 < 0 || d < B || (d == B && k2 < K2))) { B = d; K2 = k2; }
                }
                fidx[r] = K2;
            }
            __syncthreads();
        }
    }
    __syncthreads();

    // ---- outputs ----
    for (int r = 0; r < BM; ++r) {
        int    idx = fidx[r];
        size_t n   = (size_t)rowbase + r;
        float  qv  = __ldg(emb + (size_t)idx * DD + tid);
        float  zv  = __ldg(z + n * DD + tid);
        if (oq)  oq[n * DD + tid]  = qv;
        if (ost) ost[n * DD + tid] = __fadd_rn(__fadd_rn(qv, -zv), zv);
    }
    if (oidx && tid < BM)
        oidx[(size_t)rowbase + tid] = (float)fidx[tid];
}

extern "C" void kernel_launch(void* const* d_in, const int* in_sizes, int n_in,
                              void* d_out, int out_size)
{
    const float* z   = (const float*)d_in[0];
    const float* emb = (const float*)d_in[1];
    float* out = (float*)d_out;

    const int N = in_sizes[0] / DD;
    const size_t ND = (size_t)N * DD;

    float *oq = nullptr, *ost = nullptr, *oidx = nullptr;
    long osz = (long)out_size;
    if (osz >= (long)(2 * ND + N)) { oq = out; ost = out + ND; oidx = out + 2 * ND; }
    else if (osz == (long)(ND + N)) { oq = out; oidx = out + ND; }
    else if (osz == (long)ND)       { oq = out; }
    else if (osz == (long)N)        { oidx = out; }
    else                            { oq = out; }

    prep_all<<<KC + N, 32>>>(z, emb);

    cudaFuncSetAttribute(vq_main, cudaFuncAttributeMaxDynamicSharedMemorySize, STOT);
    vq_main<<<N / BM, NTHR, STOT>>>(z, emb, oq, ost, oidx);
}

// round 11
// speedup vs baseline: 1.2340x; 1.2340x over previous
#include <cuda_runtime.h>
#include <cuda_bf16.h>
#include <cstdint>

// VectorQuantizer N=65536, K=8192, D=256.
// R10: R7's bf16 mma.sync+ldmatrix filter with 512 threads (16 warps, 4/SMSP)
// to cover latency stalls; warp tile m32n16. Exact fp32 rescore replicating
// R2 arithmetic bit-for-bit (rel_err 0.0).

typedef unsigned long long u64;
typedef uint32_t u32;

#define NN     65536
#define KC     8192
#define DD     256
#define BM     128
#define BN     64
#define NTILES (KC / BN)     // 128
#define NTHR   512
#define CAP    32
#define WIN    6e-4f
#define STRD   264           // bf16 elems per smem row (528 B; staggered banks)

__device__ __nv_bfloat16 g_zbf[(size_t)NN * DD];
__device__ __nv_bfloat16 g_ebf[(size_t)KC * DD];
__device__ float g_z2[NN];
__device__ float g_e2[KC];

// smem byte offsets
#define SA    0
#define SB0   (SA + BM * STRD * 2)       // 67584
#define SB1   (SB0 + BN * STRD * 2)      // 101376
#define SE20  (SB1 + BN * STRD * 2)      // 135168
#define SE21  (SE20 + 256)               // 135424
#define SZ2   (SE21 + 256)               // 135680
#define SMIN  (SZ2 + BM * 4)             // 136192
#define SCNT  (SMIN + BM * 4)            // 136704
#define SCD   (SCNT + BM * 4)            // 137216
#define SCK   (SCD + BM * CAP * 4)       // 153600
#define SFI   (SCK + BM * CAP * 4)       // 169984
#define STOT  (SFI + BM * 4)             // 170496

__device__ __forceinline__ u32 s2u(const void* p) {
    u32 a;
    asm("{ .reg .u64 t; cvta.to.shared.u64 t, %1; cvt.u32.u64 %0, t; }"
        : "=r"(a) : "l"(p));
    return a;
}
__device__ __forceinline__ void cpa16(u32 dst, const void* src) {
    asm volatile("cp.async.ca.shared.global [%0], [%1], 16;\n" :: "r"(dst), "l"(src));
}
__device__ __forceinline__ void ldsm4(u32* r, u32 saddr) {
    asm volatile("ldmatrix.sync.aligned.m8n8.x4.shared.b16 {%0,%1,%2,%3}, [%4];"
                 : "=r"(r[0]), "=r"(r[1]), "=r"(r[2]), "=r"(r[3]) : "r"(saddr));
}
__device__ __forceinline__ void mma16816(float* c, const u32* a, const u32* b) {
    asm volatile("mma.sync.aligned.m16n8k16.row.col.f32.bf16.bf16.f32 "
                 "{%0,%1,%2,%3}, {%4,%5,%6,%7}, {%8,%9}, {%0,%1,%2,%3};"
                 : "+f"(c[0]), "+f"(c[1]), "+f"(c[2]), "+f"(c[3])
                 : "r"(a[0]), "r"(a[1]), "r"(a[2]), "r"(a[3]),
                   "r"(b[0]), "r"(b[1]));
}

// ---------------- merged prep kernel (z2/e2 accumulation order preserved!) ----------------
__global__ void prep_all(const float* __restrict__ z, const float* __restrict__ emb) {
    int b = blockIdx.x, lane = threadIdx.x;
    if (b < KC) {
        const float* r = emb + (size_t)b * DD;
        #pragma unroll
        for (int i = 0; i < DD / 32; ++i)
            g_ebf[(size_t)b * DD + lane + i * 32] = __float2bfloat16_rn(r[lane + i * 32]);
        if (lane == 0) {
            float s = 0.f;
            #pragma unroll 8
            for (int d = 0; d < DD; ++d) s = __fadd_rn(s, __fmul_rn(r[d], r[d]));
            g_e2[b] = s;
        }
    } else {
        int n = b - KC;
        const float* r = z + (size_t)n * DD;
        #pragma unroll
        for (int i = 0; i < DD / 32; ++i)
            g_zbf[(size_t)n * DD + lane + i * 32] = __float2bfloat16_rn(r[lane + i * 32]);
        if (lane == 0) {
            float s = 0.f;
            #pragma unroll 8
            for (int d = 0; d < DD; ++d) s = __fadd_rn(s, __fmul_rn(r[d], r[d]));
            g_z2[n] = s;
        }
    }
}

// ---------------- main kernel ----------------
__global__ __launch_bounds__(NTHR, 1)
void vq_main(const float* __restrict__ z, const float* __restrict__ emb,
             float* __restrict__ oq, float* __restrict__ ost,
             float* __restrict__ oidx)
{
    extern __shared__ char sm[];
    const u32 smb = s2u(sm);
    float* z2s    = (float*)(sm + SZ2);
    int*   rowMin = (int*)(sm + SMIN);
    int*   cnt    = (int*)(sm + SCNT);
    float* candD  = (float*)(sm + SCD);
    int*   candK  = (int*)(sm + SCK);
    int*   fidx   = (int*)(sm + SFI);

    const int tid  = threadIdx.x;
    const int wid  = tid >> 5;
    const int lane = tid & 31;
    const int rowbase = blockIdx.x * BM;
    const int Rw = (wid & 3) * 32;      // warp M offset (4 warps over M)
    const int Cw = (wid >> 2) * 16;     // warp N offset (4 warps over N)

    if (tid < BM) {
        rowMin[tid] = 0x7f7fffff;       // +FLT_MAX bits (distances positive)
        cnt[tid] = 0;
        z2s[tid] = g_z2[rowbase + tid];
    }

    // group 0: A tile + B tile 0 + e2 tile 0
    {
        const __nv_bfloat16* zb = g_zbf + (size_t)rowbase * DD;
        #pragma unroll 2
        for (int q = tid; q < BM * 32; q += NTHR) {
            int r = q >> 5, c = (q & 31) * 8;
            cpa16(smb + SA + (u32)((r * STRD + c) * 2), zb + (size_t)r * DD + c);
        }
        const __nv_bfloat16* eb = g_ebf;
        #pragma unroll 2
        for (int q = tid; q < BN * 32; q += NTHR) {
            int r = q >> 5, c = (q & 31) * 8;
            cpa16(smb + SB0 + (u32)((r * STRD + c) * 2), eb + (size_t)r * DD + c);
        }
        if (tid < 16) cpa16(smb + SE20 + tid * 16, g_e2 + tid * 4);
        asm volatile("cp.async.commit_group;\n" ::);
    }
    __syncthreads();

    // ldmatrix lane bases
    // A (m16k16 per x4): row = (lane&7) + 8*((lane>>3)&1), k = 8*(lane>>4)
    const int lrA = (lane & 7) + 8 * ((lane >> 3) & 1);
    const int kA  = 8 * (lane >> 4);
    const u32 aBase = smb + SA + (u32)(((Rw + lrA) * STRD + kA) * 2);
    // B (n16k16 per x4): n = (lane&7) + 8*(lane>>4), k = 8*((lane>>3)&1)
    const int lrB = (lane & 7) + 8 * (lane >> 4);
    const int kB  = 8 * ((lane >> 3) & 1);
    const u32 bOff = (u32)(((Cw + lrB) * STRD + kB) * 2);

    for (int t = 0; t < NTILES; ++t) {
        if (t + 1 < NTILES) {
            const __nv_bfloat16* eb = g_ebf + (size_t)(t + 1) * BN * DD;
            u32 bb  = smb + (((t + 1) & 1) ? SB1 : SB0);
            u32 e2d = smb + (((t + 1) & 1) ? SE21 : SE20);
            #pragma unroll 2
            for (int q = tid; q < BN * 32; q += NTHR) {
                int r = q >> 5, c = (q & 31) * 8;
                cpa16(bb + (u32)((r * STRD + c) * 2), eb + (size_t)r * DD + c);
            }
            if (tid < 16) cpa16(e2d + tid * 16, g_e2 + (t + 1) * BN + tid * 4);
            asm volatile("cp.async.commit_group;\n" ::);
            asm volatile("cp.async.wait_group 1;\n" ::);
        } else {
            asm volatile("cp.async.wait_group 0;\n" ::);
        }
        __syncthreads();

        const u32 bBase0 = smb + ((t & 1) ? SB1 : SB0) + bOff;
        const float* e2t = (const float*)(sm + ((t & 1) ? SE21 : SE20));

        float acc[2][2][4];
        #pragma unroll
        for (int mi = 0; mi < 2; ++mi)
            #pragma unroll
            for (int ni = 0; ni < 2; ++ni)
                #pragma unroll
                for (int c = 0; c < 4; ++c) acc[mi][ni][c] = 0.f;

        #pragma unroll 4
        for (int ks = 0; ks < 16; ++ks) {
            u32 aT[2][4], bT[4];
            ldsm4(aT[0], aBase + (u32)(ks * 32));
            ldsm4(aT[1], aBase + (u32)(16 * STRD * 2 + ks * 32));
            ldsm4(bT,    bBase0 + (u32)(ks * 32));
            #pragma unroll
            for (int mi = 0; mi < 2; ++mi) {
                mma16816(acc[mi][0], aT[mi], &bT[0]);
                mma16816(acc[mi][1], aT[mi], &bT[2]);
            }
        }

        // ---- epilogue: dv in-place, row-min update, windowed inserts ----
        int cb = t * BN;
        float e2loc[2][2];
        #pragma unroll
        for (int ni = 0; ni < 2; ++ni) {
            float2 v = *(const float2*)(e2t + Cw + ni * 8 + (lane & 3) * 2);
            e2loc[ni][0] = v.x; e2loc[ni][1] = v.y;
        }
        #pragma unroll
        for (int mi = 0; mi < 2; ++mi) {
            #pragma unroll
            for (int s = 0; s < 2; ++s) {
                int r = Rw + mi * 16 + (lane >> 2) + 8 * s;
                float z2v = z2s[r];
                float mn = 3.4e38f;
                #pragma unroll
                for (int ni = 0; ni < 2; ++ni) {
                    #pragma unroll
                    for (int q = 0; q < 2; ++q) {
                        float dv = fmaf(-2.f, acc[mi][ni][2 * s + q], z2v + e2loc[ni][q]);
                        acc[mi][ni][2 * s + q] = dv;
                        mn = fminf(mn, dv);
                    }
                }
                if (__float_as_int(mn) < rowMin[r])
                    atomicMin(&rowMin[r], __float_as_int(mn));
            }
        }
        if (t == 0) __syncthreads();   // tile 0: establish thresholds first
        #pragma unroll
        for (int mi = 0; mi < 2; ++mi) {
            #pragma unroll
            for (int s = 0; s < 2; ++s) {
                int r = Rw + mi * 16 + (lane >> 2) + 8 * s;
                float thr = __int_as_float(rowMin[r]) + WIN;
                #pragma unroll
                for (int ni = 0; ni < 2; ++ni) {
                    #pragma unroll
                    for (int q = 0; q < 2; ++q) {
                        float dv = acc[mi][ni][2 * s + q];
                        if (dv <= thr) {
                            int pos = atomicAdd(&cnt[r], 1);
                            if (pos < CAP) {
                                candD[r * CAP + pos] = dv;
                                candK[r * CAP + pos] = cb + Cw + ni * 8 + (lane & 3) * 2 + q;
                            }
                        }
                    }
                }
            }
        }
        __syncthreads();
    }

    // ---- exact rescore (replicates R2 arithmetic exactly) ----
    if (tid < BM) {
        int r = tid;
        size_t n = (size_t)rowbase + r;
        int c = cnt[r];
        if (c > CAP) {
            fidx[r] = -1;
        } else {
            float thrF = __int_as_float(rowMin[r]) + WIN;
            float z2e = g_z2[n];
            const float* zr = z + n * DD;
            float bd = 0.f; int bk = -1;
            for (int i = 0; i < c; ++i) {
                if (candD[r * CAP + i] > thrF) continue;
                int k = candK[r * CAP + i];
                const float* er = emb + (size_t)k * DD;
                float lo = 0.f, hi = 0.f;
                #pragma unroll 4
                for (int d2 = 0; d2 < DD / 2; ++d2) {
                    lo = __fmaf_rn(__ldg(zr + 2 * d2),     __ldg(er + 2 * d2),     lo);
                    hi = __fmaf_rn(__ldg(zr + 2 * d2 + 1), __ldg(er + 2 * d2 + 1), hi);
                }
                float dot = __fadd_rn(lo, hi);
                float tt  = __fadd_rn(z2e, g_e2[k]);
                float dd  = __fadd_rn(tt, -2.0f * dot);
                if (bk < 0 || dd < bd || (dd == bd && k < bk)) { bd = dd; bk = k; }
            }
            fidx[r] = bk;
        }
    }
    __syncthreads();

    // ---- overflow fallback: full exact scan (cold) ----
    {
        float* redD = (float*)(sm + SB0);
        int*   redI = (int*)(sm + SB0 + NTHR * 4);
        for (int r = 0; r < BM; ++r) {
            if (fidx[r] != -1) continue;
            size_t n = (size_t)rowbase + r;
            const float* zr = z + n * DD;
            float z2e = g_z2[n];
            float bd = 0.f; int bk = -1;
            for (int k = tid; k < KC; k += NTHR) {
                const float* er = emb + (size_t)k * DD;
                float lo = 0.f, hi = 0.f;
                #pragma unroll 4
                for (int d2 = 0; d2 < DD / 2; ++d2) {
                    lo = __fmaf_rn(zr[2 * d2],     er[2 * d2],     lo);
                    hi = __fmaf_rn(zr[2 * d2 + 1], er[2 * d2 + 1], hi);
                }
                float dot = __fadd_rn(lo, hi);
                float dd  = __fadd_rn(__fadd_rn(z2e, g_e2[k]), -2.0f * dot);
                if (bk < 0 || dd < bd || (dd == bd && k < bk)) { bd = dd; bk = k; }
            }
            redD[tid] = bd; redI[tid] = bk;
            __syncthreads();
            if (tid == 0) {
                float B = redD[0]; int K2 = redI[0];
                for (int s2 = 1; s2 < NTHR; ++s2) {
                    float d = redD[s2]; int k2 = redI[s2];
                    if (k2 >= 0 && (K2 < 0 || d < B || (d == B && k2 < K2))) { B = d; K2 = k2; }
                }
                fidx[r] = K2;
            }
            __syncthreads();
        }
    }
    __syncthreads();

    // ---- outputs (512 threads: 2 rows per pass) ----
    for (int rr = 0; rr < BM; rr += 2) {
        int    r   = rr + (tid >> 8);
        int    c   = tid & 255;
        int    idx = fidx[r];
        size_t n   = (size_t)rowbase + r;
        float  qv  = __ldg(emb + (size_t)idx * DD + c);
        float  zv  = __ldg(z + n * DD + c);
        if (oq)  oq[n * DD + c]  = qv;
        if (ost) ost[n * DD + c] = __fadd_rn(__fadd_rn(qv, -zv), zv);
    }
    if (oidx && tid < BM)
        oidx[(size_t)rowbase + tid] = (float)fidx[tid];
}

extern "C" void kernel_launch(void* const* d_in, const int* in_sizes, int n_in,
                              void* d_out, int out_size)
{
    const float* z   = (const float*)d_in[0];
    const float* emb = (const float*)d_in[1];
    float* out = (float*)d_out;

    const int N = in_sizes[0] / DD;
    const size_t ND = (size_t)N * DD;

    float *oq = nullptr, *ost = nullptr, *oidx = nullptr;
    long osz = (long)out_size;
    if (osz >= (long)(2 * ND + N)) { oq = out; ost = out + ND; oidx = out + 2 * ND; }
    else if (osz == (long)(ND + N)) { oq = out; oidx = out + ND; }
    else if (osz == (long)ND)       { oq = out; }
    else if (osz == (long)N)        { oidx = out; }
    else                            { oq = out; }

    prep_all<<<KC + N, 32>>>(z, emb);

    cudaFuncSetAttribute(vq_main, cudaFuncAttributeMaxDynamicSharedMemorySize, STOT);
    vq_main<<<N / BM, NTHR, STOT>>>(z, emb, oq, ost, oidx);
}